// round 13
// baseline (speedup 1.0000x reference)
#include <cuda_runtime.h>
#include <cuda_bf16.h>
#include <stdint.h>

#define BB 2
#define SS 1024
#define DD 512
#define HH 8
#define DKK 64
#define RR 16
#define GG 2
#define GDD 32
#define NHH 4
#define KMAX 64
#define NEGF (-1e30f)
#define TSLOTS 2048
#define KSPLIT 4

typedef unsigned long long ull;

// ---------------- scratch (device globals; no allocation allowed) ----------
// g_htab empty marker is 0 (matches zero-init at module load); k_epi re-clears
// it at the end of every call so each replay starts empty.
__device__ float g_qup[BB*HH*SS*DKK];   // [b][h][s][k]
__device__ float g_kup[BB*HH*SS*DKK];
__device__ float g_tmp[2*KSPLIT*BB*SS*(HH*RR)];  // [z][ks][2048][128] partials
__device__ unsigned g_hq[BB*HH*GG*SS];  // packed 4 hash bytes
__device__ unsigned g_hk[BB*HH*GG*SS];
__device__ unsigned g_qsign[HH*GG*SS];  // q sign masks from batch B-1
__device__ ull g_htab[HH*GG][TSLOTS];   // (ksign<<32)|0x80000000|idx; 0=empty
__device__ int g_cand[BB*HH*SS*KMAX];
__device__ int g_ccount[BB*HH*SS];
// overflow buffers for the (astronomically rare) many-match fallback path
__device__ int   g_midx[(size_t)BB*HH*SS*1024];
__device__ float g_msc[(size_t)BB*HH*SS*1024];

__device__ __forceinline__ unsigned f2u_ord(float f) {
    unsigned u = __float_as_uint(f);
    return (u & 0x80000000u) ? ~u : (u | 0x80000000u);
}

// ---------------- A1: stage1 K-split GEMM ------------------------------------
// partial[ks] = X_tile[64 x 128k] @ A_tile[128k x 64]
// grid (2048/64=32, 128/64=2, KSPLIT*2=8): z = (ks<<1)|zz.  256 thr.
// 512 blocks => ~3.5 blocks/SM => 28 warps/SM for latency hiding.
__global__ void k_proj1(const float* __restrict__ Xq, const float* __restrict__ Xk,
                        const float* __restrict__ Aq, const float* __restrict__ Ak) {
    int m0 = blockIdx.x * 64;
    int n0 = blockIdx.y * 64;
    int zz = blockIdx.z & 1;
    int ks = blockIdx.z >> 1;
    int tid = threadIdx.x;
    const float* X  = zz ? Xk : Xq;
    const float* Am = zz ? Ak : Aq;

    __shared__ __align__(16) float At[32][68];   // X transposed: At[d][row]
    __shared__ __align__(16) float Bs[32][64];   // proj: Bs[d][col]

    int tx = tid & 15, ty = tid >> 4;
    float c[4][4] = {};
    for (int ci = 0; ci < DD / (KSPLIT * 32); ci++) {
        int d0 = ks * (DD / KSPLIT) + ci * 32;
#pragma unroll
        for (int t = 0; t < 2; t++) {          // X tile 64 rows x 32 d, transposed
            int lin = tid + t * 256;
            int row = lin >> 3, dq = lin & 7;
            float4 v = *(const float4*)&X[(m0 + row) * DD + d0 + dq * 4];
            At[dq*4+0][row] = v.x; At[dq*4+1][row] = v.y;
            At[dq*4+2][row] = v.z; At[dq*4+3][row] = v.w;
        }
#pragma unroll
        for (int t = 0; t < 8; t++) {          // proj tile 32 d x 64 cols
            int lin = tid + t * 256;
            int r = lin >> 6, cc = lin & 63;
            int gc = n0 + cc;
            int h = gc >> 4, rr = gc & 15;
            Bs[r][cc] = Am[h * (DD * RR) + (d0 + r) * RR + rr];
        }
        __syncthreads();
#pragma unroll
        for (int d = 0; d < 32; d++) {
            float4 av = *(const float4*)&At[d][ty * 4];
            float4 bv = *(const float4*)&Bs[d][tx * 4];
            c[0][0] += av.x*bv.x; c[0][1] += av.x*bv.y; c[0][2] += av.x*bv.z; c[0][3] += av.x*bv.w;
            c[1][0] += av.y*bv.x; c[1][1] += av.y*bv.y; c[1][2] += av.y*bv.z; c[1][3] += av.y*bv.w;
            c[2][0] += av.z*bv.x; c[2][1] += av.z*bv.y; c[2][2] += av.z*bv.z; c[2][3] += av.z*bv.w;
            c[3][0] += av.w*bv.x; c[3][1] += av.w*bv.y; c[3][2] += av.w*bv.z; c[3][3] += av.w*bv.w;
        }
        __syncthreads();
    }
    float* dst = &g_tmp[(((size_t)(zz * KSPLIT + ks) * (BB*SS) + m0) * (HH*RR)) + n0];
#pragma unroll
    for (int i = 0; i < 4; i++)
        *(float4*)&dst[(ty*4 + i) * (HH*RR) + tx*4] =
            make_float4(c[i][0], c[i][1], c[i][2], c[i][3]);
}

// ---------------- A2: reduce partials + stage2 + hash/sign/insert ------------
// grid (2048/64=32, 2{q,k}), 256 thr.
__global__ void k_stage23(const float* __restrict__ Bq, const float* __restrict__ Bk,
                          const float* __restrict__ lsh) {
    int m0 = blockIdx.x * 64;
    int zz = blockIdx.y;
    int tid = threadIdx.x;
    const float* Bm = zz ? Bk : Bq;
    float* Out = zz ? g_kup : g_qup;

    __shared__ __align__(16) float Ts[64][132];  // 64 x 128 used, pad 132
    __shared__ __align__(16) float Bs[16][68];

    int tx = tid & 15, ty = tid >> 4;
    int b = m0 >> 10;
    int sbase = m0 & (SS - 1);

    // reduce 4 partials -> Ts
#pragma unroll
    for (int t = 0; t < 8; t++) {
        int lin = tid + t * 256;          // 2048 float4 = 64 rows x 32
        int r = lin >> 5, c4i = lin & 31;
        float4 s = make_float4(0.f, 0.f, 0.f, 0.f);
#pragma unroll
        for (int ks = 0; ks < KSPLIT; ks++) {
            const float* src = &g_tmp[(((size_t)(zz * KSPLIT + ks) * (BB*SS) + m0 + r) * (HH*RR)) + c4i * 4];
            float4 v = *(const float4*)src;
            s.x += v.x; s.y += v.y; s.z += v.z; s.w += v.w;
        }
        *(float4*)&Ts[r][c4i * 4] = s;
    }
    __syncthreads();

    // per head: stage2 GEMM + write Out + stage3
    for (int h = 0; h < HH; h++) {
#pragma unroll
        for (int t = 0; t < 4; t++) {     // B_h[16][64]
            int i = tid + t * 256;
            int kk = i >> 6, cc = i & 63;
            Bs[kk][cc] = Bm[h * RR * DKK + kk * DKK + cc];
        }
        __syncthreads();
        float c4[4][4] = {};
#pragma unroll
        for (int kk = 0; kk < 16; kk++) {
            float a0 = Ts[ty*4+0][h*16+kk], a1 = Ts[ty*4+1][h*16+kk];
            float a2 = Ts[ty*4+2][h*16+kk], a3 = Ts[ty*4+3][h*16+kk];
            float4 bv = *(const float4*)&Bs[kk][tx * 4];
            c4[0][0] += a0*bv.x; c4[0][1] += a0*bv.y; c4[0][2] += a0*bv.z; c4[0][3] += a0*bv.w;
            c4[1][0] += a1*bv.x; c4[1][1] += a1*bv.y; c4[1][2] += a1*bv.z; c4[1][3] += a1*bv.w;
            c4[2][0] += a2*bv.x; c4[2][1] += a2*bv.y; c4[2][2] += a2*bv.z; c4[2][3] += a2*bv.w;
            c4[3][0] += a3*bv.x; c4[3][1] += a3*bv.y; c4[3][2] += a3*bv.z; c4[3][3] += a3*bv.w;
        }
#pragma unroll
        for (int i = 0; i < 4; i++) {
            int r = ty * 4 + i;
            *(float4*)&Out[(((b * HH + h) * SS) + sbase + r) * DKK + tx * 4] =
                make_float4(c4[i][0], c4[i][1], c4[i][2], c4[i][3]);
        }
        __syncthreads();   // global writes visible block-wide before stage3 reads
        // stage3: 128 items = 2 groups x 64 rows; rows are L1-hot
        if (tid < 128) {
            int g = tid >> 6, r = tid & 63;
            int s = sbase + r;
            const float4* rowp = (const float4*)&Out[(((b*HH + h) * SS) + s) * DKK + g * GDD];
            const float4* pr = (const float4*)&lsh[(h * GG + g) * GDD * NHH];
            float a0 = 0.f, a1 = 0.f, a2 = 0.f, a3 = 0.f;
            unsigned sg = 0u;
#pragma unroll
            for (int dq = 0; dq < GDD / 4; dq++) {
                float4 vv = rowp[dq];
                float vs[4] = {vv.x, vv.y, vv.z, vv.w};
#pragma unroll
                for (int e = 0; e < 4; e++) {
                    float v = vs[e];
                    float4 p = pr[dq * 4 + e];
                    if (v > 0.f) sg |= (1u << (dq * 4 + e));
                    a0 += v * p.x; a1 += v * p.y; a2 += v * p.z; a3 += v * p.w;
                }
            }
            unsigned hw = ((unsigned)(((int)floorf(a0 * 0.25f)) & 63))
                        | ((unsigned)(((int)floorf(a1 * 0.25f)) & 63) << 8)
                        | ((unsigned)(((int)floorf(a2 * 0.25f)) & 63) << 16)
                        | ((unsigned)(((int)floorf(a3 * 0.25f)) & 63) << 24);
            int idx = ((b * HH + h) * GG + g) * SS + s;
            if (zz == 0) {
                g_hq[idx] = hw;
                if (b == BB - 1) g_qsign[(h * GG + g) * SS + s] = sg;
            } else {
                g_hk[idx] = hw;
                if (b == BB - 1) {
                    ull entry = (((ull)sg) << 32) | 0x80000000u | (unsigned)s;
                    unsigned slot = (sg * 2654435761u) >> 21;
                    while (atomicCAS(&g_htab[h * GG + g][slot & (TSLOTS - 1)], 0ull, entry) != 0ull)
                        slot++;
                }
            }
        }
        __syncthreads();
    }
}

// ---------------- B: candidate generation (warp per row, lazy) --------------
__global__ void k_cand() {
    __shared__ unsigned unionw[4][32];
    __shared__ unsigned gmask[4][32];
    __shared__ int shcnt[4];
    int tid = threadIdx.x, wid = tid >> 5, lane = tid & 31;
    int row = blockIdx.x * 4 + wid;
    int s = row & (SS - 1), h = (row >> 10) & 7, b = row >> 13;
    unionw[wid][lane] = 0u;
    __syncwarp();
    for (int g = 0; g < GG; g++) {
        gmask[wid][lane] = 0u;
        __syncwarp();
        int hg = h * GG + g;
        unsigned qsig = g_qsign[hg * SS + s];
        unsigned hqv = g_hq[((b * HH + h) * GG + g) * SS + s];
        const ull* tab = g_htab[hg];
        const unsigned* hkp = &g_hk[((b * HH + h) * GG + g) * SS];
        unsigned start = (qsig * 2654435761u) >> 21;
        int gcnt = 0;
        for (int w = 0; w < TSLOTS / 32; w++) {
            int p = (start + w * 32 + lane) & (TSLOTS - 1);
            ull e = tab[p];
            bool empty = (e == 0ull);
            unsigned em = __ballot_sync(0xffffffffu, empty);
            unsigned valid = em ? ((em & (unsigned)(-(int)em)) - 1u) : 0xffffffffu;
            bool mt = false; int j = 0;
            if (!empty && ((valid >> lane) & 1u) && (unsigned)(e >> 32) == qsig) {
                j = (int)(e & 0x3FFu);
                mt = (__vcmpeq4(hqv, hkp[j]) != 0u);
            }
            unsigned bal = __ballot_sync(0xffffffffu, mt);
            if (mt) atomicOr(&gmask[wid][j >> 5], 1u << (j & 31));
            gcnt += __popc(bal);
            if (em) break;
        }
        if (gcnt > KMAX) {
            // rare fallback: compute scores for flagged j's, exact 64th-largest
            const float* qbase = &g_qup[row * DKK + g * GDD];
            const float* kbase = &g_kup[(b * HH + h) * SS * DKK + g * GDD];
            int* mix = &g_midx[(size_t)row * 1024];
            float* msf = &g_msc[(size_t)row * 1024];
            if (lane == 0) shcnt[wid] = 0;
            __syncwarp();
            unsigned w = gmask[wid][lane];
            while (w) {
                int bpos = __ffs(w) - 1;
                w &= w - 1;
                int j = lane * 32 + bpos;
                float a = 0.f;
                const float* kr = kbase + j * DKK;
#pragma unroll
                for (int d = 0; d < GDD; d++) a += qbase[d] * kr[d];
                int rk = atomicAdd(&shcnt[wid], 1);
                mix[rk] = j; msf[rk] = a;
            }
            __syncwarp();
            gmask[wid][lane] = 0u;
            __syncwarp();
            unsigned prefix = 0u; int kk = KMAX;
            for (int bit = 31; bit >= 0; bit--) {
                int local = 0;
                for (int i = lane; i < gcnt; i += 32) {
                    unsigned key = f2u_ord(msf[i]);
                    unsigned hi2 = (bit == 31) ? 0u : (key >> (bit + 1));
                    if (hi2 == prefix && ((key >> bit) & 1u)) local++;
                }
#pragma unroll
                for (int off = 16; off; off >>= 1) local += __shfl_xor_sync(0xffffffffu, local, off);
                if (local >= kk) prefix = (prefix << 1) | 1u;
                else { kk -= local; prefix <<= 1; }
            }
            for (int i = lane; i < gcnt; i += 32)
                if (f2u_ord(msf[i]) >= prefix)
                    atomicOr(&gmask[wid][mix[i] >> 5], 1u << (mix[i] & 31));
        }
        __syncwarp();
        unionw[wid][lane] |= gmask[wid][lane];
        __syncwarp();
    }
    unsigned w = unionw[wid][lane];
    int c = __popc(w);
    int pre = c;
#pragma unroll
    for (int off = 1; off < 32; off <<= 1) {
        int n = __shfl_up_sync(0xffffffffu, pre, off);
        if (lane >= off) pre += n;
    }
    int excl = pre - c;
    int total = __shfl_sync(0xffffffffu, pre, 31);
    if (lane == 0) g_ccount[row] = (total > KMAX) ? KMAX : total;
    if (total > 0) {
        int* crow = &g_cand[row * KMAX];
        int rank = excl;
        while (w && rank < KMAX) {
            int bpos = __ffs(w) - 1;
            w &= w - 1;
            crow[rank++] = lane * 32 + bpos;
        }
    }
}

// ---------------- C: epilogue (zero-fill fast path; full fallback) -----------
// grid (S/64, DD/64, B), 256 thr. Per block: check its 512 row counts;
// all-zero -> zero out tile. Else compute attn (vup on the fly) + out proj.
// Also clears g_htab for the next call.
__global__ void k_epi(const float* __restrict__ value, const float* __restrict__ Wv,
                      const float* __restrict__ Wo, float* __restrict__ out) {
    int stile = blockIdx.x, ntile = blockIdx.y, b = blockIdx.z;
    int sbase = stile * 64, n0 = ntile * 64;
    int tid = threadIdx.x;
    __shared__ int nzflag;
    if (tid == 0) nzflag = 0;
    __syncthreads();
    int any = 0;
#pragma unroll
    for (int t = 0; t < 2; t++) {
        int item = tid + t * 256;       // 512 = 8 heads x 64 rows
        int h = item >> 6, r = item & 63;
        if (g_ccount[(b * HH + h) * SS + sbase + r] > 0) any = 1;
    }
    if (any) atomicOr(&nzflag, 1);
    // clear htab for next call (nothing reads it after k_cand)
    {
        int lin = ((b * gridDim.y + ntile) * gridDim.x + stile) * 256 + tid;
        if (lin < HH * GG * TSLOTS) ((ull*)g_htab)[lin] = 0ull;
    }
    __syncthreads();
    if (!nzflag) {
        float4 z4 = make_float4(0.f, 0.f, 0.f, 0.f);
#pragma unroll
        for (int t = 0; t < 4; t++) {
            int lin = tid + t * 256;    // 1024 float4 = 64 rows x 16
            int r = lin >> 4, c4i = lin & 15;
            *(float4*)&out[(b * SS + sbase + r) * DD + n0 + c4i * 4] = z4;
        }
        return;
    }
    // ---------- fallback: full sparse attention + output projection ----------
    __shared__ float Oh[64][65];
    __shared__ float Ws[64][65];
    __shared__ float sl[8][KMAX];
    int lane = tid & 31, w = tid >> 5;
    int tx = tid & 15, ty = tid >> 4;
    float acc[4][4] = {};
    for (int h = 0; h < HH; h++) {
        for (int rr = 0; rr < 8; rr++) {
            int r = w * 8 + rr;
            int row = (b * HH + h) * SS + sbase + r;
            int cnt = g_ccount[row];
            float o0 = 0.f, o1 = 0.f;
            if (cnt > 0) {
                const int* crow = &g_cand[row * KMAX];
                const float* q = &g_qup[row * DKK];
                const float* kb2 = &g_kup[(b * HH + h) * SS * DKK];
                float mx = NEGF;
                for (int c = 0; c < cnt; c++) {
                    int j = crow[c];
                    const float* kr = kb2 + j * DKK;
                    float a = q[lane] * kr[lane] + q[lane + 32] * kr[lane + 32];
#pragma unroll
                    for (int off = 16; off; off >>= 1) a += __shfl_xor_sync(0xffffffffu, a, off);
                    a *= 0.125f;
                    if (lane == 0) sl[w][c] = a;
                    mx = fmaxf(mx, a);
                }
                __syncwarp();
                float sum = 0.f;
                for (int c = 0; c < cnt; c++) {
                    float e = expf(sl[w][c] - mx);
                    sum += e;
                }
                __syncwarp();
                float inv = (sum > 0.f) ? (1.f / sum) : 0.f;
                for (int c = 0; c < cnt; c++) {
                    int j = crow[c];
                    float p = expf(sl[w][c] - mx) * inv;
                    const float* vr = &value[(b * SS + j) * DD];
                    const float* wv = &Wv[h * DD * DKK];
                    float v0 = 0.f, v1 = 0.f;
                    for (int d = 0; d < DD; d++) {
                        float vv = vr[d];
                        v0 += vv * wv[d * DKK + lane];
                        v1 += vv * wv[d * DKK + lane + 32];
                    }
                    o0 += p * v0; o1 += p * v1;
                }
            }
            Oh[r][lane] = o0; Oh[r][lane + 32] = o1;
        }
        __syncthreads();
#pragma unroll
        for (int t = 0; t < 16; t++) {
            int lin = tid + t * 256;    // 4096 = 64x64
            int kk = lin >> 6, cc = lin & 63;
            Ws[kk][cc] = Wo[(h * DKK + kk) * DD + n0 + cc];
        }
        __syncthreads();
        for (int kk = 0; kk < DKK; kk++) {
            float a0 = Oh[ty*4+0][kk], a1 = Oh[ty*4+1][kk];
            float a2 = Oh[ty*4+2][kk], a3 = Oh[ty*4+3][kk];
            float b0 = Ws[kk][tx*4+0], b1 = Ws[kk][tx*4+1];
            float b2 = Ws[kk][tx*4+2], b3 = Ws[kk][tx*4+3];
            acc[0][0] += a0*b0; acc[0][1] += a0*b1; acc[0][2] += a0*b2; acc[0][3] += a0*b3;
            acc[1][0] += a1*b0; acc[1][1] += a1*b1; acc[1][2] += a1*b2; acc[1][3] += a1*b3;
            acc[2][0] += a2*b0; acc[2][1] += a2*b1; acc[2][2] += a2*b2; acc[2][3] += a2*b3;
            acc[3][0] += a3*b0; acc[3][1] += a3*b1; acc[3][2] += a3*b2; acc[3][3] += a3*b3;
        }
        __syncthreads();
    }
#pragma unroll
    for (int i = 0; i < 4; i++) {
        float4 v = make_float4(acc[i][0], acc[i][1], acc[i][2], acc[i][3]);
        *(float4*)&out[(b * SS + sbase + ty * 4 + i) * DD + n0 + tx * 4] = v;
    }
}

// ---------------- launch ----------------------------------------------------
extern "C" void kernel_launch(void* const* d_in, const int* in_sizes, int n_in,
                              void* d_out, int out_size) {
    const float* query = (const float*)d_in[0];
    const float* key   = (const float*)d_in[1];
    const float* value = (const float*)d_in[2];
    const float* Aq    = (const float*)d_in[3];
    const float* Bq    = (const float*)d_in[4];
    const float* Ak    = (const float*)d_in[5];
    const float* Bk    = (const float*)d_in[6];
    const float* Wv    = (const float*)d_in[7];
    const float* Wo    = (const float*)d_in[8];
    const float* lsh   = (const float*)d_in[9];
    float* out = (float*)d_out;

    k_proj1<<<dim3(BB * SS / 64, (HH * RR) / 64, KSPLIT * 2), 256>>>(query, key, Aq, Ak);
    k_stage23<<<dim3(BB * SS / 64, 2), 256>>>(Bq, Bk, lsh);
    k_cand<<<BB * HH * SS / 4, 128>>>();
    k_epi<<<dim3(SS / 64, DD / 64, BB), 256>>>(value, Wv, Wo, out);
}

// round 15
// speedup vs baseline: 1.6604x; 1.6604x over previous
#include <cuda_runtime.h>
#include <cuda_bf16.h>
#include <stdint.h>

#define BB 2
#define SS 1024
#define DD 512
#define HH 8
#define DKK 64
#define RR 16
#define GG 2
#define GDD 32
#define NHH 4
#define KMAX 64
#define NEGF (-1e30f)
#define TSLOTS 2048

typedef unsigned long long ull;

// ---------------- scratch (device globals; no allocation allowed) ----------
// g_htab empty marker is 0 (matches zero-init at module load); k_epi re-clears
// it at the end of every call so each replay starts empty.
__device__ float g_qup[BB*HH*SS*DKK];   // [b][h][s][k]
__device__ float g_kup[BB*HH*SS*DKK];
__device__ unsigned g_hq[BB*HH*GG*SS];  // packed 4 hash bytes
__device__ unsigned g_hk[BB*HH*GG*SS];
__device__ unsigned g_qsign[HH*GG*SS];  // q sign masks from batch B-1
__device__ ull g_htab[HH*GG][TSLOTS];   // (ksign<<32)|0x80000000|idx; 0=empty
__device__ int g_cand[BB*HH*SS*KMAX];
__device__ int g_ccount[BB*HH*SS];
// overflow buffers for the (astronomically rare) many-match fallback path
__device__ int   g_midx[(size_t)BB*HH*SS*1024];
__device__ float g_msc[(size_t)BB*HH*SS*1024];

__device__ __forceinline__ unsigned f2u_ord(float f) {
    unsigned u = __float_as_uint(f);
    return (u & 0x80000000u) ? ~u : (u | 0x80000000u);
}
__device__ __forceinline__ unsigned tf32cvt(float f) {
    unsigned u;
    asm("cvt.rna.tf32.f32 %0, %1;" : "=r"(u) : "f"(f));
    return u;
}
__device__ __forceinline__ void mma_tf32(float& d0, float& d1, float& d2, float& d3,
                                         unsigned a0, unsigned a1, unsigned a2, unsigned a3,
                                         unsigned b0, unsigned b1) {
    asm("mma.sync.aligned.m16n8k8.row.col.f32.tf32.tf32.f32 "
        "{%0,%1,%2,%3}, {%4,%5,%6,%7}, {%8,%9}, {%0,%1,%2,%3};"
        : "+f"(d0), "+f"(d1), "+f"(d2), "+f"(d3)
        : "r"(a0), "r"(a1), "r"(a2), "r"(a3), "r"(b0), "r"(b1));
}

// ---------------- A: fused low-rank projection + hash/sign/insert -----------
// stage1 (tf32 tensor cores): Ts[64][64] = X_tile[64x512] @ A_tile[512x64].
//   Asu: X tile tf32, row-major, stride 36 (conflict-free).
//   Bsu: proj tile tf32, k-major rows, stride 72 (conflict-free).
//   8 warps = 2(m) x 4(n); each warp 32x16 via 2x2 m16n8k8 frags; K chunks 32.
// stage2: per covered head: out[64x64] = Ts_h[64x16] @ B_h[16x64] -> global
// stage3: per head: hash + signs read back from just-written global (L1-hot)
// grid (2048/64=32, 128/64=2, 2{q,k}) = 128 blocks, 256 thr
__global__ void k_proj(const float* __restrict__ Xq, const float* __restrict__ Xk,
                       const float* __restrict__ Aq, const float* __restrict__ Ak,
                       const float* __restrict__ Bq, const float* __restrict__ Bk,
                       const float* __restrict__ lsh) {
    int m0 = blockIdx.x * 64;
    int n0 = blockIdx.y * 64;
    int z = blockIdx.z;
    int tid = threadIdx.x;
    const float* X  = z ? Xk : Xq;
    const float* Am = z ? Ak : Aq;
    const float* Bm = z ? Bk : Bq;
    float* Out = z ? g_kup : g_qup;

    __shared__ __align__(16) unsigned Asu[64 * 36];  // X tf32: [row][k], stride 36
    __shared__ __align__(16) unsigned Bsu[32 * 72];  // proj tf32: [k][n], stride 72
    __shared__ __align__(16) float Ts[64][68];
    __shared__ __align__(16) float Bs2[16][68];      // stage2 B_h tile

    int w = tid >> 5, lane = tid & 31;
    int g = lane >> 2, t4 = lane & 3;
    int wm = (w >> 2) * 32;          // warp m-base (0 or 32)
    int wn = (w & 3) * 16;           // warp n-base (0,16,32,48)
    int b = m0 >> 10;
    int sbase = m0 & (SS - 1);
    int h0 = n0 >> 4;

    float dAcc[2][2][4] = {};        // [mi][ni][c0..c3]

    int xrow = tid >> 3, xq = tid & 7;   // X loader: 256 thr x (row, 4-col grp); x2
    for (int ch = 0; ch < 16; ch++) {
        int d0 = ch * 32;
        // load X 64x32 -> Asu (tf32)
#pragma unroll
        for (int tt = 0; tt < 2; tt++) {
            int row = xrow + tt * 32;
            float4 v = *(const float4*)&X[(m0 + row) * DD + d0 + xq * 4];
            uint4 u = make_uint4(tf32cvt(v.x), tf32cvt(v.y), tf32cvt(v.z), tf32cvt(v.w));
            *(uint4*)&Asu[row * 36 + xq * 4] = u;
        }
        // load Am 32x64 -> Bsu (tf32)
#pragma unroll
        for (int tt = 0; tt < 8; tt++) {
            int lin = tid + tt * 256;
            int r = lin >> 6, cc = lin & 63;
            int gc = n0 + cc;
            int h = gc >> 4, rr = gc & 15;
            Bsu[r * 72 + cc] = tf32cvt(Am[h * (DD * RR) + (d0 + r) * RR + rr]);
        }
        __syncthreads();
#pragma unroll
        for (int kk = 0; kk < 32; kk += 8) {
            unsigned af[2][4], bf[2][2];
#pragma unroll
            for (int mi = 0; mi < 2; mi++) {
                int r0 = wm + mi * 16 + g;
                af[mi][0] = Asu[r0 * 36 + kk + t4];
                af[mi][1] = Asu[(r0 + 8) * 36 + kk + t4];
                af[mi][2] = Asu[r0 * 36 + kk + t4 + 4];
                af[mi][3] = Asu[(r0 + 8) * 36 + kk + t4 + 4];
            }
#pragma unroll
            for (int ni = 0; ni < 2; ni++) {
                int c0 = wn + ni * 8 + g;
                bf[ni][0] = Bsu[(kk + t4) * 72 + c0];
                bf[ni][1] = Bsu[(kk + t4 + 4) * 72 + c0];
            }
#pragma unroll
            for (int mi = 0; mi < 2; mi++)
#pragma unroll
                for (int ni = 0; ni < 2; ni++)
                    mma_tf32(dAcc[mi][ni][0], dAcc[mi][ni][1], dAcc[mi][ni][2], dAcc[mi][ni][3],
                             af[mi][0], af[mi][1], af[mi][2], af[mi][3],
                             bf[ni][0], bf[ni][1]);
        }
        __syncthreads();
    }
    // write fragments -> Ts
#pragma unroll
    for (int mi = 0; mi < 2; mi++)
#pragma unroll
        for (int ni = 0; ni < 2; ni++) {
            int r0 = wm + mi * 16 + g;
            int c0 = wn + ni * 8 + 2 * t4;
            Ts[r0][c0]     = dAcc[mi][ni][0];
            Ts[r0][c0 + 1] = dAcc[mi][ni][1];
            Ts[r0 + 8][c0]     = dAcc[mi][ni][2];
            Ts[r0 + 8][c0 + 1] = dAcc[mi][ni][3];
        }
    __syncthreads();

    // stage2+3 per head
    int tx = tid & 15, ty = tid >> 4;
#pragma unroll
    for (int hl = 0; hl < 4; hl++) {
        int h = h0 + hl;
#pragma unroll
        for (int tt = 0; tt < 4; tt++) {
            int i = tid + tt * 256;
            int kk = i >> 6, cc = i & 63;
            Bs2[kk][cc] = Bm[h * RR * DKK + kk * DKK + cc];
        }
        __syncthreads();
        float c4[4][4] = {};
#pragma unroll
        for (int kk = 0; kk < 16; kk++) {
            float a0 = Ts[ty*4+0][hl*16+kk], a1 = Ts[ty*4+1][hl*16+kk];
            float a2 = Ts[ty*4+2][hl*16+kk], a3 = Ts[ty*4+3][hl*16+kk];
            float4 bv = *(const float4*)&Bs2[kk][tx * 4];
            c4[0][0] += a0*bv.x; c4[0][1] += a0*bv.y; c4[0][2] += a0*bv.z; c4[0][3] += a0*bv.w;
            c4[1][0] += a1*bv.x; c4[1][1] += a1*bv.y; c4[1][2] += a1*bv.z; c4[1][3] += a1*bv.w;
            c4[2][0] += a2*bv.x; c4[2][1] += a2*bv.y; c4[2][2] += a2*bv.z; c4[2][3] += a2*bv.w;
            c4[3][0] += a3*bv.x; c4[3][1] += a3*bv.y; c4[3][2] += a3*bv.z; c4[3][3] += a3*bv.w;
        }
#pragma unroll
        for (int i = 0; i < 4; i++) {
            int r = ty * 4 + i;
            *(float4*)&Out[(((b * HH + h) * SS) + sbase + r) * DKK + tx * 4] =
                make_float4(c4[i][0], c4[i][1], c4[i][2], c4[i][3]);
        }
        __syncthreads();   // global writes visible block-wide before stage3 reads
        // stage3: 128 items = 2 groups x 64 rows; rows are L1-hot
        if (tid < 128) {
            int gg = tid >> 6, r = tid & 63;
            int s = sbase + r;
            const float4* rowp = (const float4*)&Out[(((b*HH + h) * SS) + s) * DKK + gg * GDD];
            const float4* pr = (const float4*)&lsh[(h * GG + gg) * GDD * NHH];
            float a0 = 0.f, a1 = 0.f, a2 = 0.f, a3 = 0.f;
            unsigned sg = 0u;
#pragma unroll
            for (int dq = 0; dq < GDD / 4; dq++) {
                float4 vv = rowp[dq];
                float vs[4] = {vv.x, vv.y, vv.z, vv.w};
#pragma unroll
                for (int e = 0; e < 4; e++) {
                    float v = vs[e];
                    float4 p = pr[dq * 4 + e];
                    if (v > 0.f) sg |= (1u << (dq * 4 + e));
                    a0 += v * p.x; a1 += v * p.y; a2 += v * p.z; a3 += v * p.w;
                }
            }
            unsigned hw = ((unsigned)(((int)floorf(a0 * 0.25f)) & 63))
                        | ((unsigned)(((int)floorf(a1 * 0.25f)) & 63) << 8)
                        | ((unsigned)(((int)floorf(a2 * 0.25f)) & 63) << 16)
                        | ((unsigned)(((int)floorf(a3 * 0.25f)) & 63) << 24);
            int idx = ((b * HH + h) * GG + gg) * SS + s;
            if (z == 0) {
                g_hq[idx] = hw;
                if (b == BB - 1) g_qsign[(h * GG + gg) * SS + s] = sg;
            } else {
                g_hk[idx] = hw;
                if (b == BB - 1) {
                    ull entry = (((ull)sg) << 32) | 0x80000000u | (unsigned)s;
                    unsigned slot = (sg * 2654435761u) >> 21;
                    while (atomicCAS(&g_htab[h * GG + gg][slot & (TSLOTS - 1)], 0ull, entry) != 0ull)
                        slot++;
                }
            }
        }
        __syncthreads();
    }
}

// ---------------- B: candidate generation (warp per row, lazy) --------------
__global__ void k_cand() {
    __shared__ unsigned unionw[4][32];
    __shared__ unsigned gmask[4][32];
    __shared__ int shcnt[4];
    int tid = threadIdx.x, wid = tid >> 5, lane = tid & 31;
    int row = blockIdx.x * 4 + wid;
    int s = row & (SS - 1), h = (row >> 10) & 7, b = row >> 13;
    unionw[wid][lane] = 0u;
    __syncwarp();
    for (int g = 0; g < GG; g++) {
        gmask[wid][lane] = 0u;
        __syncwarp();
        int hg = h * GG + g;
        unsigned qsig = g_qsign[hg * SS + s];
        unsigned hqv = g_hq[((b * HH + h) * GG + g) * SS + s];
        const ull* tab = g_htab[hg];
        const unsigned* hkp = &g_hk[((b * HH + h) * GG + g) * SS];
        unsigned start = (qsig * 2654435761u) >> 21;
        int gcnt = 0;
        for (int w = 0; w < TSLOTS / 32; w++) {
            int p = (start + w * 32 + lane) & (TSLOTS - 1);
            ull e = tab[p];
            bool empty = (e == 0ull);
            unsigned em = __ballot_sync(0xffffffffu, empty);
            unsigned valid = em ? ((em & (unsigned)(-(int)em)) - 1u) : 0xffffffffu;
            bool mt = false; int j = 0;
            if (!empty && ((valid >> lane) & 1u) && (unsigned)(e >> 32) == qsig) {
                j = (int)(e & 0x3FFu);
                mt = (__vcmpeq4(hqv, hkp[j]) != 0u);
            }
            unsigned bal = __ballot_sync(0xffffffffu, mt);
            if (mt) atomicOr(&gmask[wid][j >> 5], 1u << (j & 31));
            gcnt += __popc(bal);
            if (em) break;
        }
        if (gcnt > KMAX) {
            // rare fallback: compute scores for flagged j's, exact 64th-largest
            const float* qbase = &g_qup[row * DKK + g * GDD];
            const float* kbase = &g_kup[(b * HH + h) * SS * DKK + g * GDD];
            int* mix = &g_midx[(size_t)row * 1024];
            float* msf = &g_msc[(size_t)row * 1024];
            if (lane == 0) shcnt[wid] = 0;
            __syncwarp();
            unsigned w = gmask[wid][lane];
            while (w) {
                int bpos = __ffs(w) - 1;
                w &= w - 1;
                int j = lane * 32 + bpos;
                float a = 0.f;
                const float* kr = kbase + j * DKK;
#pragma unroll
                for (int d = 0; d < GDD; d++) a += qbase[d] * kr[d];
                int rk = atomicAdd(&shcnt[wid], 1);
                mix[rk] = j; msf[rk] = a;
            }
            __syncwarp();
            gmask[wid][lane] = 0u;
            __syncwarp();
            unsigned prefix = 0u; int kk = KMAX;
            for (int bit = 31; bit >= 0; bit--) {
                int local = 0;
                for (int i = lane; i < gcnt; i += 32) {
                    unsigned key = f2u_ord(msf[i]);
                    unsigned hi2 = (bit == 31) ? 0u : (key >> (bit + 1));
                    if (hi2 == prefix && ((key >> bit) & 1u)) local++;
                }
#pragma unroll
                for (int off = 16; off; off >>= 1) local += __shfl_xor_sync(0xffffffffu, local, off);
                if (local >= kk) prefix = (prefix << 1) | 1u;
                else { kk -= local; prefix <<= 1; }
            }
            for (int i = lane; i < gcnt; i += 32)
                if (f2u_ord(msf[i]) >= prefix)
                    atomicOr(&gmask[wid][mix[i] >> 5], 1u << (mix[i] & 31));
        }
        __syncwarp();
        unionw[wid][lane] |= gmask[wid][lane];
        __syncwarp();
    }
    unsigned w = unionw[wid][lane];
    int c = __popc(w);
    int pre = c;
#pragma unroll
    for (int off = 1; off < 32; off <<= 1) {
        int n = __shfl_up_sync(0xffffffffu, pre, off);
        if (lane >= off) pre += n;
    }
    int excl = pre - c;
    int total = __shfl_sync(0xffffffffu, pre, 31);
    if (lane == 0) g_ccount[row] = (total > KMAX) ? KMAX : total;
    if (total > 0) {
        int* crow = &g_cand[row * KMAX];
        int rank = excl;
        while (w && rank < KMAX) {
            int bpos = __ffs(w) - 1;
            w &= w - 1;
            crow[rank++] = lane * 32 + bpos;
        }
    }
}

// ---------------- C: epilogue (zero-fill fast path; full fallback) -----------
// grid (S/64, DD/64, B), 256 thr. Per block: check its 512 row counts;
// all-zero -> zero out tile. Else compute attn (vup on the fly) + out proj.
// Also clears g_htab for the next call.
__global__ void k_epi(const float* __restrict__ value, const float* __restrict__ Wv,
                      const float* __restrict__ Wo, float* __restrict__ out) {
    int stile = blockIdx.x, ntile = blockIdx.y, b = blockIdx.z;
    int sbase = stile * 64, n0 = ntile * 64;
    int tid = threadIdx.x;
    __shared__ int nzflag;
    if (tid == 0) nzflag = 0;
    __syncthreads();
    int any = 0;
#pragma unroll
    for (int t = 0; t < 2; t++) {
        int item = tid + t * 256;       // 512 = 8 heads x 64 rows
        int h = item >> 6, r = item & 63;
        if (g_ccount[(b * HH + h) * SS + sbase + r] > 0) any = 1;
    }
    if (any) atomicOr(&nzflag, 1);
    // clear htab for next call (nothing reads it after k_cand)
    {
        int lin = ((b * gridDim.y + ntile) * gridDim.x + stile) * 256 + tid;
        if (lin < HH * GG * TSLOTS) ((ull*)g_htab)[lin] = 0ull;
    }
    __syncthreads();
    if (!nzflag) {
        float4 z4 = make_float4(0.f, 0.f, 0.f, 0.f);
#pragma unroll
        for (int t = 0; t < 4; t++) {
            int lin = tid + t * 256;    // 1024 float4 = 64 rows x 16
            int r = lin >> 4, c4i = lin & 15;
            *(float4*)&out[(b * SS + sbase + r) * DD + n0 + c4i * 4] = z4;
        }
        return;
    }
    // ---------- fallback: full sparse attention + output projection ----------
    __shared__ float Oh[64][65];
    __shared__ float Ws[64][65];
    __shared__ float sl[8][KMAX];
    int lane = tid & 31, w = tid >> 5;
    int tx = tid & 15, ty = tid >> 4;
    float acc[4][4] = {};
    for (int h = 0; h < HH; h++) {
        for (int rr = 0; rr < 8; rr++) {
            int r = w * 8 + rr;
            int row = (b * HH + h) * SS + sbase + r;
            int cnt = g_ccount[row];
            float o0 = 0.f, o1 = 0.f;
            if (cnt > 0) {
                const int* crow = &g_cand[row * KMAX];
                const float* q = &g_qup[row * DKK];
                const float* kb2 = &g_kup[(b * HH + h) * SS * DKK];
                float mx = NEGF;
                for (int c = 0; c < cnt; c++) {
                    int j = crow[c];
                    const float* kr = kb2 + j * DKK;
                    float a = q[lane] * kr[lane] + q[lane + 32] * kr[lane + 32];
#pragma unroll
                    for (int off = 16; off; off >>= 1) a += __shfl_xor_sync(0xffffffffu, a, off);
                    a *= 0.125f;
                    if (lane == 0) sl[w][c] = a;
                    mx = fmaxf(mx, a);
                }
                __syncwarp();
                float sum = 0.f;
                for (int c = 0; c < cnt; c++) {
                    float e = expf(sl[w][c] - mx);
                    sum += e;
                }
                __syncwarp();
                float inv = (sum > 0.f) ? (1.f / sum) : 0.f;
                for (int c = 0; c < cnt; c++) {
                    int j = crow[c];
                    float p = expf(sl[w][c] - mx) * inv;
                    const float* vr = &value[(b * SS + j) * DD];
                    const float* wv = &Wv[h * DD * DKK];
                    float v0 = 0.f, v1 = 0.f;
                    for (int d = 0; d < DD; d++) {
                        float vv = vr[d];
                        v0 += vv * wv[d * DKK + lane];
                        v1 += vv * wv[d * DKK + lane + 32];
                    }
                    o0 += p * v0; o1 += p * v1;
                }
            }
            Oh[r][lane] = o0; Oh[r][lane + 32] = o1;
        }
        __syncthreads();
#pragma unroll
        for (int t = 0; t < 16; t++) {
            int lin = tid + t * 256;    // 4096 = 64x64
            int kk = lin >> 6, cc = lin & 63;
            Ws[kk][cc] = Wo[(h * DKK + kk) * DD + n0 + cc];
        }
        __syncthreads();
        for (int kk = 0; kk < DKK; kk++) {
            float a0 = Oh[ty*4+0][kk], a1 = Oh[ty*4+1][kk];
            float a2 = Oh[ty*4+2][kk], a3 = Oh[ty*4+3][kk];
            float b0 = Ws[kk][tx*4+0], b1 = Ws[kk][tx*4+1];
            float b2 = Ws[kk][tx*4+2], b3 = Ws[kk][tx*4+3];
            acc[0][0] += a0*b0; acc[0][1] += a0*b1; acc[0][2] += a0*b2; acc[0][3] += a0*b3;
            acc[1][0] += a1*b0; acc[1][1] += a1*b1; acc[1][2] += a1*b2; acc[1][3] += a1*b3;
            acc[2][0] += a2*b0; acc[2][1] += a2*b1; acc[2][2] += a2*b2; acc[2][3] += a2*b3;
            acc[3][0] += a3*b0; acc[3][1] += a3*b1; acc[3][2] += a3*b2; acc[3][3] += a3*b3;
        }
        __syncthreads();
    }
#pragma unroll
    for (int i = 0; i < 4; i++) {
        float4 v = make_float4(acc[i][0], acc[i][1], acc[i][2], acc[i][3]);
        *(float4*)&out[(b * SS + sbase + ty * 4 + i) * DD + n0 + tx * 4] = v;
    }
}

// ---------------- launch ----------------------------------------------------
extern "C" void kernel_launch(void* const* d_in, const int* in_sizes, int n_in,
                              void* d_out, int out_size) {
    const float* query = (const float*)d_in[0];
    const float* key   = (const float*)d_in[1];
    const float* value = (const float*)d_in[2];
    const float* Aq    = (const float*)d_in[3];
    const float* Bq    = (const float*)d_in[4];
    const float* Ak    = (const float*)d_in[5];
    const float* Bk    = (const float*)d_in[6];
    const float* Wv    = (const float*)d_in[7];
    const float* Wo    = (const float*)d_in[8];
    const float* lsh   = (const float*)d_in[9];
    float* out = (float*)d_out;

    k_proj<<<dim3(BB * SS / 64, (HH * RR) / 64, 2), 256>>>(query, key, Aq, Ak, Bq, Bk, lsh);
    k_cand<<<BB * HH * SS / 4, 128>>>();
    k_epi<<<dim3(SS / 64, DD / 64, BB), 256>>>(value, Wv, Wo, out);
}

// round 16
// speedup vs baseline: 1.7828x; 1.0737x over previous
#include <cuda_runtime.h>
#include <cuda_bf16.h>
#include <stdint.h>

#define BB 2
#define SS 1024
#define DD 512
#define HH 8
#define DKK 64
#define RR 16
#define GG 2
#define GDD 32
#define NHH 4
#define KMAX 64
#define NEGF (-1e30f)
#define TSLOTS 2048

typedef unsigned long long ull;

// ---------------- scratch (device globals; no allocation allowed) ----------
// g_htab empty marker is 0 (matches zero-init at module load); k_epi re-clears
// it at the end of every call so each replay starts empty.
__device__ float g_qup[BB*HH*SS*DKK];   // [b][h][s][k]
__device__ float g_kup[BB*HH*SS*DKK];
__device__ unsigned g_hq[BB*HH*GG*SS];  // packed 4 hash bytes
__device__ unsigned g_hk[BB*HH*GG*SS];
__device__ unsigned g_qsign[HH*GG*SS];  // q sign masks from batch B-1
__device__ ull g_htab[HH*GG][TSLOTS];   // (ksign<<32)|0x80000000|idx; 0=empty
__device__ int g_cand[BB*HH*SS*KMAX];
__device__ int g_ccount[BB*HH*SS];
// overflow buffers for the (astronomically rare) many-match fallback path
__device__ int   g_midx[(size_t)BB*HH*SS*1024];
__device__ float g_msc[(size_t)BB*HH*SS*1024];

__device__ __forceinline__ unsigned f2u_ord(float f) {
    unsigned u = __float_as_uint(f);
    return (u & 0x80000000u) ? ~u : (u | 0x80000000u);
}
__device__ __forceinline__ void cpasync16(unsigned dst, const void* src) {
    asm volatile("cp.async.cg.shared.global [%0], [%1], 16;" :: "r"(dst), "l"(src));
}
__device__ __forceinline__ void cp_commit() {
    asm volatile("cp.async.commit_group;");
}
__device__ __forceinline__ void cp_wait0() {
    asm volatile("cp.async.wait_group 0;");
}
__device__ __forceinline__ void mma_tf32(float& d0, float& d1, float& d2, float& d3,
                                         unsigned a0, unsigned a1, unsigned a2, unsigned a3,
                                         unsigned b0, unsigned b1) {
    asm("mma.sync.aligned.m16n8k8.row.col.f32.tf32.tf32.f32 "
        "{%0,%1,%2,%3}, {%4,%5,%6,%7}, {%8,%9}, {%0,%1,%2,%3};"
        : "+f"(d0), "+f"(d1), "+f"(d2), "+f"(d3)
        : "r"(a0), "r"(a1), "r"(a2), "r"(a3), "r"(b0), "r"(b1));
}

// ---------------- A: fused low-rank projection + hash/sign/insert -----------
// stage1 (tf32 MMA + cp.async double buffering):
//   Ts[64][64] = X_tile[64x512] @ A_tile[512x64], K chunks of 32.
//   Buffers (raw f32 fed to mma as tf32): A[buf]: [row][k] stride 36;
//   B[buf]: [k][n] stride 72. Chunk i+1 copied async during chunk i compute.
//   8 warps = 2(m) x 4(n); each warp 32x16 via 2x2 m16n8k8 frags.
// stage2: per covered head: out[64x64] = Ts_h[64x16] @ B_h[16x64] -> global
// stage3: per head: hash + signs read back from just-written global (L1-hot)
// grid (2048/64=32, 128/64=2, 2{q,k}) = 128 blocks, 256 thr
__global__ void k_proj(const float* __restrict__ Xq, const float* __restrict__ Xk,
                       const float* __restrict__ Aq, const float* __restrict__ Ak,
                       const float* __restrict__ Bq, const float* __restrict__ Bk,
                       const float* __restrict__ lsh) {
    int m0 = blockIdx.x * 64;
    int n0 = blockIdx.y * 64;
    int z = blockIdx.z;
    int tid = threadIdx.x;
    const float* X  = z ? Xk : Xq;
    const float* Am = z ? Ak : Aq;
    const float* Bm = z ? Bk : Bq;
    float* Out = z ? g_kup : g_qup;

    // 36864B raw smem: mainloop = A bufs @0,9216 ; B bufs @18432,27648
    // epilogue overlay = Ts(17408B)@0 ; Bs2(4352B)@17408
    __shared__ __align__(16) char smem_raw[36864];
    unsigned smem_u32 = (unsigned)__cvta_generic_to_shared(smem_raw);
    const unsigned abase[2] = {smem_u32, smem_u32 + 9216u};
    const unsigned bbase[2] = {smem_u32 + 18432u, smem_u32 + 27648u};
    const unsigned* Asu0 = (const unsigned*)smem_raw;             // stride 36
    const unsigned* Asu1 = (const unsigned*)(smem_raw + 9216);
    const unsigned* Bsu0 = (const unsigned*)(smem_raw + 18432);   // stride 72
    const unsigned* Bsu1 = (const unsigned*)(smem_raw + 27648);
    float (*Ts)[68]  = (float(*)[68])smem_raw;
    float (*Bs2)[68] = (float(*)[68])(smem_raw + 17408);

    int w = tid >> 5, lane = tid & 31;
    int g = lane >> 2, t4 = lane & 3;
    int wm = (w >> 2) * 32;          // warp m-base (0 or 32)
    int wn = (w & 3) * 16;           // warp n-base (0,16,32,48)
    int b = m0 >> 10;
    int sbase = m0 & (SS - 1);
    int h0 = n0 >> 4;

    float dAcc[2][2][4] = {};        // [mi][ni][c0..c3]

    int xrow = tid >> 3, xq = tid & 7;     // X: (row, 16B-chunk); x2 rows
    int br = tid >> 4, bq4 = tid & 15;     // Am: (k-row pair base, 16B-chunk)
    // prefetch chunk 0
    {
        int d0 = 0;
#pragma unroll
        for (int tt = 0; tt < 2; tt++) {
            int row = xrow + tt * 32;
            cpasync16(abase[0] + row * 144u + xq * 16u,
                      &X[(m0 + row) * DD + d0 + xq * 4]);
        }
#pragma unroll
        for (int tt = 0; tt < 2; tt++) {
            int r = br + tt * 16;
            int h = h0 + (bq4 >> 2), rr4 = (bq4 & 3) * 4;
            cpasync16(bbase[0] + r * 288u + bq4 * 16u,
                      &Am[h * (DD * RR) + (d0 + r) * RR + rr4]);
        }
        cp_commit();
    }

    for (int ch = 0; ch < 16; ch++) {
        cp_wait0();
        __syncthreads();
        if (ch < 15) {
            int d0 = (ch + 1) * 32;
            int buf = (ch + 1) & 1;
#pragma unroll
            for (int tt = 0; tt < 2; tt++) {
                int row = xrow + tt * 32;
                cpasync16(abase[buf] + row * 144u + xq * 16u,
                          &X[(m0 + row) * DD + d0 + xq * 4]);
            }
#pragma unroll
            for (int tt = 0; tt < 2; tt++) {
                int r = br + tt * 16;
                int h = h0 + (bq4 >> 2), rr4 = (bq4 & 3) * 4;
                cpasync16(bbase[buf] + r * 288u + bq4 * 16u,
                          &Am[h * (DD * RR) + (d0 + r) * RR + rr4]);
            }
            cp_commit();
        }
        const unsigned* Au = (ch & 1) ? Asu1 : Asu0;
        const unsigned* Bu = (ch & 1) ? Bsu1 : Bsu0;
#pragma unroll
        for (int kk = 0; kk < 32; kk += 8) {
            unsigned af[2][4], bf[2][2];
#pragma unroll
            for (int mi = 0; mi < 2; mi++) {
                int r0 = wm + mi * 16 + g;
                af[mi][0] = Au[r0 * 36 + kk + t4];
                af[mi][1] = Au[(r0 + 8) * 36 + kk + t4];
                af[mi][2] = Au[r0 * 36 + kk + t4 + 4];
                af[mi][3] = Au[(r0 + 8) * 36 + kk + t4 + 4];
            }
#pragma unroll
            for (int ni = 0; ni < 2; ni++) {
                int c0 = wn + ni * 8 + g;
                bf[ni][0] = Bu[(kk + t4) * 72 + c0];
                bf[ni][1] = Bu[(kk + t4 + 4) * 72 + c0];
            }
#pragma unroll
            for (int mi = 0; mi < 2; mi++)
#pragma unroll
                for (int ni = 0; ni < 2; ni++)
                    mma_tf32(dAcc[mi][ni][0], dAcc[mi][ni][1], dAcc[mi][ni][2], dAcc[mi][ni][3],
                             af[mi][0], af[mi][1], af[mi][2], af[mi][3],
                             bf[ni][0], bf[ni][1]);
        }
        __syncthreads();
    }
    // write fragments -> Ts (overlays buffers; all compute finished + barrier)
#pragma unroll
    for (int mi = 0; mi < 2; mi++)
#pragma unroll
        for (int ni = 0; ni < 2; ni++) {
            int r0 = wm + mi * 16 + g;
            int c0 = wn + ni * 8 + 2 * t4;
            Ts[r0][c0]     = dAcc[mi][ni][0];
            Ts[r0][c0 + 1] = dAcc[mi][ni][1];
            Ts[r0 + 8][c0]     = dAcc[mi][ni][2];
            Ts[r0 + 8][c0 + 1] = dAcc[mi][ni][3];
        }
    __syncthreads();

    // stage2+3 per head
    int tx = tid & 15, ty = tid >> 4;
#pragma unroll
    for (int hl = 0; hl < 4; hl++) {
        int h = h0 + hl;
#pragma unroll
        for (int tt = 0; tt < 4; tt++) {
            int i = tid + tt * 256;
            int kk = i >> 6, cc = i & 63;
            Bs2[kk][cc] = Bm[h * RR * DKK + kk * DKK + cc];
        }
        __syncthreads();
        float c4[4][4] = {};
#pragma unroll
        for (int kk = 0; kk < 16; kk++) {
            float a0 = Ts[ty*4+0][hl*16+kk], a1 = Ts[ty*4+1][hl*16+kk];
            float a2 = Ts[ty*4+2][hl*16+kk], a3 = Ts[ty*4+3][hl*16+kk];
            float4 bv = *(const float4*)&Bs2[kk][tx * 4];
            c4[0][0] += a0*bv.x; c4[0][1] += a0*bv.y; c4[0][2] += a0*bv.z; c4[0][3] += a0*bv.w;
            c4[1][0] += a1*bv.x; c4[1][1] += a1*bv.y; c4[1][2] += a1*bv.z; c4[1][3] += a1*bv.w;
            c4[2][0] += a2*bv.x; c4[2][1] += a2*bv.y; c4[2][2] += a2*bv.z; c4[2][3] += a2*bv.w;
            c4[3][0] += a3*bv.x; c4[3][1] += a3*bv.y; c4[3][2] += a3*bv.z; c4[3][3] += a3*bv.w;
        }
#pragma unroll
        for (int i = 0; i < 4; i++) {
            int r = ty * 4 + i;
            *(float4*)&Out[(((b * HH + h) * SS) + sbase + r) * DKK + tx * 4] =
                make_float4(c4[i][0], c4[i][1], c4[i][2], c4[i][3]);
        }
        __syncthreads();   // global writes visible block-wide before stage3 reads
        // stage3: 128 items = 2 groups x 64 rows; rows are L1-hot
        if (tid < 128) {
            int gg = tid >> 6, r = tid & 63;
            int s = sbase + r;
            const float4* rowp = (const float4*)&Out[(((b*HH + h) * SS) + s) * DKK + gg * GDD];
            const float4* pr = (const float4*)&lsh[(h * GG + gg) * GDD * NHH];
            float a0 = 0.f, a1 = 0.f, a2 = 0.f, a3 = 0.f;
            unsigned sg = 0u;
#pragma unroll
            for (int dq = 0; dq < GDD / 4; dq++) {
                float4 vv = rowp[dq];
                float vs[4] = {vv.x, vv.y, vv.z, vv.w};
#pragma unroll
                for (int e = 0; e < 4; e++) {
                    float v = vs[e];
                    float4 p = pr[dq * 4 + e];
                    if (v > 0.f) sg |= (1u << (dq * 4 + e));
                    a0 += v * p.x; a1 += v * p.y; a2 += v * p.z; a3 += v * p.w;
                }
            }
            unsigned hw = ((unsigned)(((int)floorf(a0 * 0.25f)) & 63))
                        | ((unsigned)(((int)floorf(a1 * 0.25f)) & 63) << 8)
                        | ((unsigned)(((int)floorf(a2 * 0.25f)) & 63) << 16)
                        | ((unsigned)(((int)floorf(a3 * 0.25f)) & 63) << 24);
            int idx = ((b * HH + h) * GG + gg) * SS + s;
            if (z == 0) {
                g_hq[idx] = hw;
                if (b == BB - 1) g_qsign[(h * GG + gg) * SS + s] = sg;
            } else {
                g_hk[idx] = hw;
                if (b == BB - 1) {
                    ull entry = (((ull)sg) << 32) | 0x80000000u | (unsigned)s;
                    unsigned slot = (sg * 2654435761u) >> 21;
                    while (atomicCAS(&g_htab[h * GG + gg][slot & (TSLOTS - 1)], 0ull, entry) != 0ull)
                        slot++;
                }
            }
        }
        __syncthreads();
    }
}

// ---------------- B: candidate generation (warp per row, lazy) --------------
__global__ void k_cand() {
    __shared__ unsigned unionw[4][32];
    __shared__ unsigned gmask[4][32];
    __shared__ int shcnt[4];
    int tid = threadIdx.x, wid = tid >> 5, lane = tid & 31;
    int row = blockIdx.x * 4 + wid;
    int s = row & (SS - 1), h = (row >> 10) & 7, b = row >> 13;
    unionw[wid][lane] = 0u;
    __syncwarp();
    for (int g = 0; g < GG; g++) {
        gmask[wid][lane] = 0u;
        __syncwarp();
        int hg = h * GG + g;
        unsigned qsig = g_qsign[hg * SS + s];
        unsigned hqv = g_hq[((b * HH + h) * GG + g) * SS + s];
        const ull* tab = g_htab[hg];
        const unsigned* hkp = &g_hk[((b * HH + h) * GG + g) * SS];
        unsigned start = (qsig * 2654435761u) >> 21;
        int gcnt = 0;
        for (int w = 0; w < TSLOTS / 32; w++) {
            int p = (start + w * 32 + lane) & (TSLOTS - 1);
            ull e = tab[p];
            bool empty = (e == 0ull);
            unsigned em = __ballot_sync(0xffffffffu, empty);
            unsigned valid = em ? ((em & (unsigned)(-(int)em)) - 1u) : 0xffffffffu;
            bool mt = false; int j = 0;
            if (!empty && ((valid >> lane) & 1u) && (unsigned)(e >> 32) == qsig) {
                j = (int)(e & 0x3FFu);
                mt = (__vcmpeq4(hqv, hkp[j]) != 0u);
            }
            unsigned bal = __ballot_sync(0xffffffffu, mt);
            if (mt) atomicOr(&gmask[wid][j >> 5], 1u << (j & 31));
            gcnt += __popc(bal);
            if (em) break;
        }
        if (gcnt > KMAX) {
            // rare fallback: compute scores for flagged j's, exact 64th-largest
            const float* qbase = &g_qup[row * DKK + g * GDD];
            const float* kbase = &g_kup[(b * HH + h) * SS * DKK + g * GDD];
            int* mix = &g_midx[(size_t)row * 1024];
            float* msf = &g_msc[(size_t)row * 1024];
            if (lane == 0) shcnt[wid] = 0;
            __syncwarp();
            unsigned w = gmask[wid][lane];
            while (w) {
                int bpos = __ffs(w) - 1;
                w &= w - 1;
                int j = lane * 32 + bpos;
                float a = 0.f;
                const float* kr = kbase + j * DKK;
#pragma unroll
                for (int d = 0; d < GDD; d++) a += qbase[d] * kr[d];
                int rk = atomicAdd(&shcnt[wid], 1);
                mix[rk] = j; msf[rk] = a;
            }
            __syncwarp();
            gmask[wid][lane] = 0u;
            __syncwarp();
            unsigned prefix = 0u; int kk = KMAX;
            for (int bit = 31; bit >= 0; bit--) {
                int local = 0;
                for (int i = lane; i < gcnt; i += 32) {
                    unsigned key = f2u_ord(msf[i]);
                    unsigned hi2 = (bit == 31) ? 0u : (key >> (bit + 1));
                    if (hi2 == prefix && ((key >> bit) & 1u)) local++;
                }
#pragma unroll
                for (int off = 16; off; off >>= 1) local += __shfl_xor_sync(0xffffffffu, local, off);
                if (local >= kk) prefix = (prefix << 1) | 1u;
                else { kk -= local; prefix <<= 1; }
            }
            for (int i = lane; i < gcnt; i += 32)
                if (f2u_ord(msf[i]) >= prefix)
                    atomicOr(&gmask[wid][mix[i] >> 5], 1u << (mix[i] & 31));
        }
        __syncwarp();
        unionw[wid][lane] |= gmask[wid][lane];
        __syncwarp();
    }
    unsigned w = unionw[wid][lane];
    int c = __popc(w);
    int pre = c;
#pragma unroll
    for (int off = 1; off < 32; off <<= 1) {
        int n = __shfl_up_sync(0xffffffffu, pre, off);
        if (lane >= off) pre += n;
    }
    int excl = pre - c;
    int total = __shfl_sync(0xffffffffu, pre, 31);
    if (lane == 0) g_ccount[row] = (total > KMAX) ? KMAX : total;
    if (total > 0) {
        int* crow = &g_cand[row * KMAX];
        int rank = excl;
        while (w && rank < KMAX) {
            int bpos = __ffs(w) - 1;
            w &= w - 1;
            crow[rank++] = lane * 32 + bpos;
        }
    }
}

// ---------------- C: epilogue (zero-fill fast path; full fallback) -----------
// grid (S/64, DD/64, B), 256 thr. Per block: check its 512 row counts;
// all-zero -> zero out tile. Else compute attn (vup on the fly) + out proj.
// Also clears g_htab for the next call.
__global__ void k_epi(const float* __restrict__ value, const float* __restrict__ Wv,
                      const float* __restrict__ Wo, float* __restrict__ out) {
    int stile = blockIdx.x, ntile = blockIdx.y, b = blockIdx.z;
    int sbase = stile * 64, n0 = ntile * 64;
    int tid = threadIdx.x;
    __shared__ int nzflag;
    if (tid == 0) nzflag = 0;
    __syncthreads();
    int any = 0;
#pragma unroll
    for (int t = 0; t < 2; t++) {
        int item = tid + t * 256;       // 512 = 8 heads x 64 rows
        int h = item >> 6, r = item & 63;
        if (g_ccount[(b * HH + h) * SS + sbase + r] > 0) any = 1;
    }
    if (any) atomicOr(&nzflag, 1);
    // clear htab for next call (nothing reads it after k_cand)
    {
        int lin = ((b * gridDim.y + ntile) * gridDim.x + stile) * 256 + tid;
        if (lin < HH * GG * TSLOTS) ((ull*)g_htab)[lin] = 0ull;
    }
    __syncthreads();
    if (!nzflag) {
        float4 z4 = make_float4(0.f, 0.f, 0.f, 0.f);
#pragma unroll
        for (int t = 0; t < 4; t++) {
            int lin = tid + t * 256;    // 1024 float4 = 64 rows x 16
            int r = lin >> 4, c4i = lin & 15;
            *(float4*)&out[(b * SS + sbase + r) * DD + n0 + c4i * 4] = z4;
        }
        return;
    }
    // ---------- fallback: full sparse attention + output projection ----------
    __shared__ float Oh[64][65];
    __shared__ float Ws[64][65];
    __shared__ float sl[8][KMAX];
    int lane = tid & 31, w = tid >> 5;
    int tx = tid & 15, ty = tid >> 4;
    float acc[4][4] = {};
    for (int h = 0; h < HH; h++) {
        for (int rr = 0; rr < 8; rr++) {
            int r = w * 8 + rr;
            int row = (b * HH + h) * SS + sbase + r;
            int cnt = g_ccount[row];
            float o0 = 0.f, o1 = 0.f;
            if (cnt > 0) {
                const int* crow = &g_cand[row * KMAX];
                const float* q = &g_qup[row * DKK];
                const float* kb2 = &g_kup[(b * HH + h) * SS * DKK];
                float mx = NEGF;
                for (int c = 0; c < cnt; c++) {
                    int j = crow[c];
                    const float* kr = kb2 + j * DKK;
                    float a = q[lane] * kr[lane] + q[lane + 32] * kr[lane + 32];
#pragma unroll
                    for (int off = 16; off; off >>= 1) a += __shfl_xor_sync(0xffffffffu, a, off);
                    a *= 0.125f;
                    if (lane == 0) sl[w][c] = a;
                    mx = fmaxf(mx, a);
                }
                __syncwarp();
                float sum = 0.f;
                for (int c = 0; c < cnt; c++) {
                    float e = expf(sl[w][c] - mx);
                    sum += e;
                }
                __syncwarp();
                float inv = (sum > 0.f) ? (1.f / sum) : 0.f;
                for (int c = 0; c < cnt; c++) {
                    int j = crow[c];
                    float p = expf(sl[w][c] - mx) * inv;
                    const float* vr = &value[(b * SS + j) * DD];
                    const float* wv = &Wv[h * DD * DKK];
                    float v0 = 0.f, v1 = 0.f;
                    for (int d = 0; d < DD; d++) {
                        float vv = vr[d];
                        v0 += vv * wv[d * DKK + lane];
                        v1 += vv * wv[d * DKK + lane + 32];
                    }
                    o0 += p * v0; o1 += p * v1;
                }
            }
            Oh[r][lane] = o0; Oh[r][lane + 32] = o1;
        }
        __syncthreads();
#pragma unroll
        for (int t = 0; t < 16; t++) {
            int lin = tid + t * 256;    // 4096 = 64x64
            int kk = lin >> 6, cc = lin & 63;
            Ws[kk][cc] = Wo[(h * DKK + kk) * DD + n0 + cc];
        }
        __syncthreads();
        for (int kk = 0; kk < DKK; kk++) {
            float a0 = Oh[ty*4+0][kk], a1 = Oh[ty*4+1][kk];
            float a2 = Oh[ty*4+2][kk], a3 = Oh[ty*4+3][kk];
            float b0 = Ws[kk][tx*4+0], b1 = Ws[kk][tx*4+1];
            float b2 = Ws[kk][tx*4+2], b3 = Ws[kk][tx*4+3];
            acc[0][0] += a0*b0; acc[0][1] += a0*b1; acc[0][2] += a0*b2; acc[0][3] += a0*b3;
            acc[1][0] += a1*b0; acc[1][1] += a1*b1; acc[1][2] += a1*b2; acc[1][3] += a1*b3;
            acc[2][0] += a2*b0; acc[2][1] += a2*b1; acc[2][2] += a2*b2; acc[2][3] += a2*b3;
            acc[3][0] += a3*b0; acc[3][1] += a3*b1; acc[3][2] += a3*b2; acc[3][3] += a3*b3;
        }
        __syncthreads();
    }
#pragma unroll
    for (int i = 0; i < 4; i++) {
        float4 v = make_float4(acc[i][0], acc[i][1], acc[i][2], acc[i][3]);
        *(float4*)&out[(b * SS + sbase + ty * 4 + i) * DD + n0 + tx * 4] = v;
    }
}

// ---------------- launch ----------------------------------------------------
extern "C" void kernel_launch(void* const* d_in, const int* in_sizes, int n_in,
                              void* d_out, int out_size) {
    const float* query = (const float*)d_in[0];
    const float* key   = (const float*)d_in[1];
    const float* value = (const float*)d_in[2];
    const float* Aq    = (const float*)d_in[3];
    const float* Bq    = (const float*)d_in[4];
    const float* Ak    = (const float*)d_in[5];
    const float* Bk    = (const float*)d_in[6];
    const float* Wv    = (const float*)d_in[7];
    const float* Wo    = (const float*)d_in[8];
    const float* lsh   = (const float*)d_in[9];
    float* out = (float*)d_out;

    k_proj<<<dim3(BB * SS / 64, (HH * RR) / 64, 2), 256>>>(query, key, Aq, Ak, Bq, Bk, lsh);
    k_cand<<<BB * HH * SS / 4, 128>>>();
    k_epi<<<dim3(SS / 64, DD / 64, BB), 256>>>(value, Wv, Wo, out);
}